// round 7
// baseline (speedup 1.0000x reference)
#include <cuda_runtime.h>
#include <stdint.h>
#include <math.h>

// Problem constants (from reference): N=512, M=1024, B=1024, K=64, 100 power iters, 50 IHT iters
#define NDIM 512
#define MDIM 1024
#define BDIM 1024
#define KSP  64
#define NITER 51  // init + 50

// ---------------- static device scratch (no allocations allowed) ----------------
__device__ float d_Wn   [NDIM * MDIM];   // normalized dictionary [512,1024]
__device__ float d_WnT  [MDIM * NDIM];   // transpose [1024,512]
__device__ float d_G    [MDIM * MDIM];   // W^T W
__device__ float d_P1   [MDIM * MDIM];   // power scratch
__device__ float d_P2   [MDIM * MDIM];   // power scratch (ends as G^16)
__device__ float d_Gamma[BDIM * MDIM];
__device__ float d_Gtmp [BDIM * MDIM];
__device__ float d_Resid[BDIM * NDIM];
__device__ float d_x0[MDIM];
__device__ float d_vA[MDIM];
__device__ float d_vB[MDIM];
__device__ float d_ss[16];
__device__ float d_cn[MDIM];
__device__ float d_eta[1];
__device__ float d_ynPart[128];
__device__ float d_resPart[NITER * 128];

// ---------------- threefry + XLA erf_inv to reproduce jax.random.normal(key(42),(1,1024)) ----------------
__device__ __forceinline__ unsigned rotl32(unsigned x, int d) { return (x << d) | (x >> (32 - d)); }

__device__ float erfinv_xla(float x) {
    float w = -log1pf(-x * x);
    float p;
    if (w < 5.0f) {
        w -= 2.5f;
        p = 2.81022636e-08f;
        p = fmaf(p, w, 3.43273939e-07f);
        p = fmaf(p, w, -3.5233877e-06f);
        p = fmaf(p, w, -4.39150654e-06f);
        p = fmaf(p, w, 0.00021858087f);
        p = fmaf(p, w, -0.00125372503f);
        p = fmaf(p, w, -0.00417768164f);
        p = fmaf(p, w, 0.246640727f);
        p = fmaf(p, w, 1.50140941f);
    } else {
        w = sqrtf(w) - 3.0f;
        p = -0.000200214257f;
        p = fmaf(p, w, 0.000100950558f);
        p = fmaf(p, w, 0.00134934322f);
        p = fmaf(p, w, -0.00367342844f);
        p = fmaf(p, w, 0.00573950773f);
        p = fmaf(p, w, -0.0076224613f);
        p = fmaf(p, w, 0.00943887047f);
        p = fmaf(p, w, 1.00167406f);
        p = fmaf(p, w, 2.83297682f);
    }
    return p * x;
}

__device__ __forceinline__ float bits_to_normal(unsigned bits) {
    float f = __uint_as_float((bits >> 9) | 0x3F800000u) - 1.0f;   // [0,1)
    const float lo = -0.99999994f;                                  // nextafter(-1,0)
    float u = fmaxf(lo, fmaf(f, 2.0f, lo));                         // span (1-lo) rounds to 2.0f in fp32
    return 1.41421356f * erfinv_xla(u);
}

__global__ void threefryNormal(float* __restrict__ x0) {
    int i = threadIdx.x;  // 512 threads, one block
    const unsigned k0 = 0u, k1 = 42u;
    const unsigned ks2 = k0 ^ k1 ^ 0x1BD11BDAu;
    unsigned x = (unsigned)i + k0;
    unsigned y = (unsigned)(i + 512) + k1;
#define TFRND(r) { x += y; y = rotl32(y, r); y ^= x; }
#define TF4A TFRND(13) TFRND(15) TFRND(26) TFRND(6)
#define TF4B TFRND(17) TFRND(29) TFRND(16) TFRND(24)
    TF4A x += k1;  y += ks2 + 1u;
    TF4B x += ks2; y += k0  + 2u;
    TF4A x += k0;  y += k1  + 3u;
    TF4B x += k1;  y += ks2 + 4u;
    TF4A x += ks2; y += k0  + 5u;
    x0[i]       = bits_to_normal(x);
    x0[i + 512] = bits_to_normal(y);
}

// ---------------- dictionary normalization ----------------
__global__ void colNorms(const float* __restrict__ W, float* __restrict__ cn) {
    int m = blockIdx.x * 256 + threadIdx.x;  // 4 blocks
    float s = 0.0f;
    for (int i = 0; i < NDIM; i++) { float v = W[i * MDIM + m]; s += v * v; }
    cn[m] = sqrtf(s);
}

__global__ void normW(const float* __restrict__ W, const float* __restrict__ cn,
                      float* __restrict__ Wn, float* __restrict__ WnT) {
    int idx = blockIdx.x * 256 + threadIdx.x;  // 2048 blocks
    int i = idx >> 10, m = idx & 1023;
    float v = W[idx] / cn[m];
    Wn[idx] = v;
    WnT[m * NDIM + i] = v;
}

// ---------------- generic 64x64 tiled SGEMM, row-major NN ----------------
// MODE 0: C = A*B
// MODE 1: C = Gin - eta*(A*B)
// MODE 2: C = A*B - Ymat; partialOut[block] = sum(C^2) over tile
template <int MODE>
__global__ void __launch_bounds__(256) sgemm_k(
    const float* __restrict__ A, const float* __restrict__ B, float* __restrict__ C,
    int M, int N, int K,
    const float* __restrict__ etaPtr, const float* __restrict__ Gin,
    const float* __restrict__ Ymat, float* __restrict__ partialOut)
{
    __shared__ float As[16][65];
    __shared__ float Bs[16][64];
    __shared__ float redp[256];
    int t = threadIdx.x;
    int tx = t & 15, ty = t >> 4;
    int bm = blockIdx.y, bn = blockIdx.x;
    const float* Ab = A + (size_t)bm * 64 * K;
    const float* Bb = B + bn * 64;
    float acc[4][4] = {};
    int la_m = t >> 2;
    int la_k = (t & 3) * 4;
    int lb_k = t >> 4;
    int lb_n = (t & 15) * 4;
    for (int kt = 0; kt < K; kt += 16) {
        float4 av = *(const float4*)(Ab + (size_t)la_m * K + kt + la_k);
        As[la_k + 0][la_m] = av.x; As[la_k + 1][la_m] = av.y;
        As[la_k + 2][la_m] = av.z; As[la_k + 3][la_m] = av.w;
        float4 bv = *(const float4*)(Bb + (size_t)(kt + lb_k) * N + lb_n);
        *(float4*)&Bs[lb_k][lb_n] = bv;
        __syncthreads();
#pragma unroll
        for (int kk = 0; kk < 16; kk++) {
            float ar[4], br[4];
#pragma unroll
            for (int i = 0; i < 4; i++) ar[i] = As[kk][ty * 4 + i];
            float4 b4 = *(const float4*)&Bs[kk][tx * 4];
            br[0] = b4.x; br[1] = b4.y; br[2] = b4.z; br[3] = b4.w;
#pragma unroll
            for (int i = 0; i < 4; i++)
#pragma unroll
                for (int j = 0; j < 4; j++) acc[i][j] = fmaf(ar[i], br[j], acc[i][j]);
        }
        __syncthreads();
    }
    int row0 = bm * 64 + ty * 4, col0 = bn * 64 + tx * 4;
    float ss = 0.0f;
    float eta = (MODE == 1) ? *etaPtr : 0.0f;
#pragma unroll
    for (int i = 0; i < 4; i++) {
#pragma unroll
        for (int j = 0; j < 4; j++) {
            size_t idx = (size_t)(row0 + i) * N + (col0 + j);
            float v = acc[i][j];
            if (MODE == 0) {
                C[idx] = v;
            } else if (MODE == 1) {
                C[idx] = Gin[idx] - eta * v;
            } else {
                float r = v - Ymat[idx];
                C[idx] = r;
                ss += r * r;
            }
        }
    }
    if (MODE == 2) {
        redp[t] = ss;
        __syncthreads();
        for (int off = 128; off; off >>= 1) { if (t < off) redp[t] += redp[t + off]; __syncthreads(); }
        if (t == 0) partialOut[blockIdx.y * gridDim.x + blockIdx.x] = redp[0];
    }
}

// ---------------- matvec (1024x1024) with input renormalization by prev sumsq ----------------
__global__ void __launch_bounds__(256) matvec(const float* __restrict__ A, const float* __restrict__ xin,
                                              const float* __restrict__ ssPrev, float* __restrict__ yout) {
    __shared__ float red[256];
    int row = blockIdx.x, t = threadIdx.x;
    const float* a = A + (size_t)row * MDIM;
    float s = 0.0f;
    for (int j = t; j < MDIM; j += 256) s = fmaf(a[j], xin[j], s);
    red[t] = s;
    __syncthreads();
    for (int off = 128; off; off >>= 1) { if (t < off) red[t] += red[t + off]; __syncthreads(); }
    if (t == 0) {
        float scale = ssPrev ? (1.0f / sqrtf(*ssPrev)) : 1.0f;
        yout[row] = red[0] * scale;
    }
}

__global__ void sumsq1024(const float* __restrict__ v, float* __restrict__ out) {
    __shared__ float red[256];
    int t = threadIdx.x;
    float s = 0.0f;
    for (int j = t; j < MDIM; j += 256) { float x = v[j]; s += x * x; }
    red[t] = s;
    __syncthreads();
    for (int off = 128; off; off >>= 1) { if (t < off) red[t] += red[t + off]; __syncthreads(); }
    if (t == 0) *out = red[0];
}

__global__ void computeEta(const float* __restrict__ ssLast, float* __restrict__ eta) {
    *eta = 1.0f / sqrtf(*ssLast);
}

// ---------------- ||Y|| partials ----------------
__global__ void ynormPart(const float* __restrict__ Y, float* __restrict__ part) {
    __shared__ float red[256];
    int t = threadIdx.x;
    size_t base = (size_t)blockIdx.x * 4096;
    float s = 0.0f;
    for (int j = t; j < 4096; j += 256) { float x = Y[base + j]; s += x * x; }
    red[t] = s;
    __syncthreads();
    for (int off = 128; off; off >>= 1) { if (t < off) red[t] += red[t + off]; __syncthreads(); }
    if (t == 0) part[blockIdx.x] = red[0];
}

// ---------------- init helpers ----------------
__global__ void zeroBuf(float* __restrict__ p, int n) {
    int i = blockIdx.x * 256 + threadIdx.x;
    if (i < n) p[i] = 0.0f;
}
__global__ void negCopy(const float* __restrict__ src, float* __restrict__ dst, int n) {
    int i = blockIdx.x * 256 + threadIdx.x;
    if (i < n) dst[i] = -src[i];
}

// ---------------- exact per-row hard threshold: keep |g| > (65th largest |g|) ----------------
__global__ void __launch_bounds__(256) htK(const float* __restrict__ Gtmp, float* __restrict__ Gamma) {
    __shared__ unsigned bits[MDIM];
    __shared__ int cnt[256];
    __shared__ int scanA[256];
    __shared__ int scanB[256];
    __shared__ int s_sel, s_above;
    int row = blockIdx.x, t = threadIdx.x;
    const float* g = Gtmp + (size_t)row * MDIM;
    for (int i = t; i < MDIM; i += 256) bits[i] = __float_as_uint(g[i]);

    unsigned prefix = 0, mask = 0;
    int r = KSP;  // 0-based descending rank 64 -> 65th largest
    for (int p = 0; p < 4; p++) {
        int sh = 24 - 8 * p;
        cnt[t] = 0;
        __syncthreads();
        for (int i = t; i < MDIM; i += 256) {
            unsigned key = bits[i] & 0x7FFFFFFFu;
            if ((key & mask) == prefix) atomicAdd(&cnt[(key >> sh) & 0xFF], 1);
        }
        __syncthreads();
        scanA[t] = cnt[t];
        __syncthreads();
        int* src = scanA; int* dst = scanB;
        for (int off = 1; off < 256; off <<= 1) {
            int v = src[t] + ((t + off < 256) ? src[t + off] : 0);  // inclusive suffix sum
            dst[t] = v;
            __syncthreads();
            int* tmp = src; src = dst; dst = tmp;
        }
        int above = (t < 255) ? src[t + 1] : 0;  // strictly-above count
        if (cnt[t] > 0 && above <= r && r < above + cnt[t]) { s_sel = t; s_above = above; }
        __syncthreads();
        prefix |= ((unsigned)s_sel) << sh;
        mask   |= 0xFFu << sh;
        r -= s_above;
        __syncthreads();
    }
    // prefix == abs-bits of T; keep strictly greater
    for (int i = t; i < MDIM; i += 256) {
        unsigned b = bits[i];
        unsigned key = b & 0x7FFFFFFFu;
        Gamma[(size_t)row * MDIM + i] = (key > prefix) ? __uint_as_float(b) : 0.0f;
    }
}

// ---------------- final norms: out[t] = sqrt(sum resPart[t+1])/||Y|| ----------------
__global__ void normsFinal(const float* __restrict__ resPart, const float* __restrict__ ynPart,
                           float* __restrict__ out) {
    __shared__ float yn;
    int t = threadIdx.x;  // 64 threads
    if (t == 0) {
        float s = 0.0f;
        for (int b = 0; b < 128; b++) s += ynPart[b];
        yn = sqrtf(s);
    }
    __syncthreads();
    if (t < 50) {
        float s = 0.0f;
        const float* p = resPart + (size_t)(t + 1) * 128;
        for (int b = 0; b < 128; b++) s += p[b];
        out[t] = sqrtf(s) / yn;
    }
}

// ---------------- host orchestration ----------------
extern "C" void kernel_launch(void* const* d_in, const int* in_sizes, int n_in,
                              void* d_out, int out_size) {
    (void)in_sizes; (void)n_in; (void)out_size;
    const float* Y = (const float*)d_in[0];  // [1024,512]
    const float* W = (const float*)d_in[1];  // [512,1024]
    float* out = (float*)d_out;

    float *Wn, *WnT, *G, *P1, *P2, *Gamma, *Gtmp, *Resid, *x0, *vA, *vB, *ss, *cn, *eta, *ynP, *rsP;
    cudaGetSymbolAddress((void**)&Wn, d_Wn);
    cudaGetSymbolAddress((void**)&WnT, d_WnT);
    cudaGetSymbolAddress((void**)&G, d_G);
    cudaGetSymbolAddress((void**)&P1, d_P1);
    cudaGetSymbolAddress((void**)&P2, d_P2);
    cudaGetSymbolAddress((void**)&Gamma, d_Gamma);
    cudaGetSymbolAddress((void**)&Gtmp, d_Gtmp);
    cudaGetSymbolAddress((void**)&Resid, d_Resid);
    cudaGetSymbolAddress((void**)&x0, d_x0);
    cudaGetSymbolAddress((void**)&vA, d_vA);
    cudaGetSymbolAddress((void**)&vB, d_vB);
    cudaGetSymbolAddress((void**)&ss, d_ss);
    cudaGetSymbolAddress((void**)&cn, d_cn);
    cudaGetSymbolAddress((void**)&eta, d_eta);
    cudaGetSymbolAddress((void**)&ynP, d_ynPart);
    cudaGetSymbolAddress((void**)&rsP, d_resPart);

    // 1) dictionary normalization
    colNorms<<<4, 256>>>(W, cn);
    normW<<<2048, 256>>>(W, cn, Wn, WnT);

    // 2) power method setup: x0 (exact jax init), G = Wn^T Wn, squarings to G^16
    threefryNormal<<<1, 512>>>(x0);
    sgemm_k<0><<<dim3(16, 16), 256>>>(WnT, Wn, G, MDIM, MDIM, NDIM, nullptr, nullptr, nullptr, nullptr);
    sgemm_k<0><<<dim3(16, 16), 256>>>(G,  G,  P1, MDIM, MDIM, MDIM, nullptr, nullptr, nullptr, nullptr);  // G^2
    sgemm_k<0><<<dim3(16, 16), 256>>>(P1, P1, P2, MDIM, MDIM, MDIM, nullptr, nullptr, nullptr, nullptr);  // G^4
    sgemm_k<0><<<dim3(16, 16), 256>>>(P2, P2, P1, MDIM, MDIM, MDIM, nullptr, nullptr, nullptr, nullptr);  // G^8
    sgemm_k<0><<<dim3(16, 16), 256>>>(P1, P1, P2, MDIM, MDIM, MDIM, nullptr, nullptr, nullptr, nullptr);  // G^16

    // 3) matvec chain: 3x G, 6x G^16, 1x G  (= 100 applications), renormalize each step
    matvec<<<MDIM, 256>>>(G, x0, nullptr, vA);   sumsq1024<<<1, 256>>>(vA, ss + 0);
    matvec<<<MDIM, 256>>>(G, vA, ss + 0, vB);    sumsq1024<<<1, 256>>>(vB, ss + 1);
    matvec<<<MDIM, 256>>>(G, vB, ss + 1, vA);    sumsq1024<<<1, 256>>>(vA, ss + 2);
    matvec<<<MDIM, 256>>>(P2, vA, ss + 2, vB);   sumsq1024<<<1, 256>>>(vB, ss + 3);
    matvec<<<MDIM, 256>>>(P2, vB, ss + 3, vA);   sumsq1024<<<1, 256>>>(vA, ss + 4);
    matvec<<<MDIM, 256>>>(P2, vA, ss + 4, vB);   sumsq1024<<<1, 256>>>(vB, ss + 5);
    matvec<<<MDIM, 256>>>(P2, vB, ss + 5, vA);   sumsq1024<<<1, 256>>>(vA, ss + 6);
    matvec<<<MDIM, 256>>>(P2, vA, ss + 6, vB);   sumsq1024<<<1, 256>>>(vB, ss + 7);
    matvec<<<MDIM, 256>>>(P2, vB, ss + 7, vA);   sumsq1024<<<1, 256>>>(vA, ss + 8);
    matvec<<<MDIM, 256>>>(G,  vA, ss + 8, vB);   sumsq1024<<<1, 256>>>(vB, ss + 9);
    computeEta<<<1, 1>>>(ss + 9, eta);

    // 4) ||Y|| partials
    ynormPart<<<128, 256>>>(Y, ynP);

    // 5) IHT: Gamma=0, residual=-Y, then 51 uniform iterations
    zeroBuf<<<4096, 256>>>(Gamma, BDIM * MDIM);
    negCopy<<<2048, 256>>>(Y, Resid, BDIM * NDIM);

    for (int t = 0; t < NITER; t++) {
        // Gtmp = Gamma - eta * (Resid @ Wn)       [1024,1024]
        sgemm_k<1><<<dim3(16, 16), 256>>>(Resid, Wn, Gtmp, BDIM, MDIM, NDIM, eta, Gamma, nullptr, nullptr);
        // Gamma = HT_K(Gtmp)
        htK<<<BDIM, 256>>>(Gtmp, Gamma);
        // Resid = Gamma @ Wn^T - Y, + per-block sumsq partials  [1024,512]
        sgemm_k<2><<<dim3(8, 16), 256>>>(Gamma, WnT, Resid, BDIM, NDIM, MDIM, nullptr, nullptr, Y,
                                         rsP + (size_t)t * 128);
    }

    // 6) outputs: X = Wn @ Gamma [512,1024], then Gamma [1024,1024], then norms [50]
    sgemm_k<0><<<dim3(16, 8), 256>>>(Wn, Gamma, out, NDIM, MDIM, MDIM, nullptr, nullptr, nullptr, nullptr);
    cudaMemcpyAsync(out + NDIM * MDIM, Gamma, (size_t)BDIM * MDIM * sizeof(float),
                    cudaMemcpyDeviceToDevice);
    normsFinal<<<1, 64>>>(rsP, ynP, out + NDIM * MDIM + BDIM * MDIM);
}

// round 9
// speedup vs baseline: 2.3151x; 2.3151x over previous
#include <cuda_runtime.h>
#include <stdint.h>
#include <math.h>

// Problem constants: N=512, M=1024, B=1024, K=64, 100 power iters, 50 IHT iters
#define NDIM 512
#define MDIM 1024
#define BDIM 1024
#define KSP  64
#define NITER 51  // init + 50

// ---------------- static device scratch ----------------
__device__ float d_Wn   [NDIM * MDIM];
__device__ float d_WnT  [MDIM * NDIM];
__device__ float d_G    [MDIM * MDIM];
__device__ float d_P1   [MDIM * MDIM];
__device__ float d_P2   [MDIM * MDIM];
__device__ float d_Gamma[BDIM * MDIM];
__device__ float d_Gtmp [BDIM * MDIM];
__device__ float d_Resid[BDIM * NDIM];
__device__ float d_x0[MDIM];
__device__ float d_vA[MDIM];
__device__ float d_vB[MDIM];
__device__ float d_ss[16];
__device__ float d_cn[MDIM];
__device__ float d_eta[1];
__device__ float d_ynPart[128];
__device__ float d_resPart[NITER * BDIM];

// ---------------- threefry + XLA erf_inv (jax.random.normal(key(42),(1,1024))) ----------------
__device__ __forceinline__ unsigned rotl32(unsigned x, int d) { return (x << d) | (x >> (32 - d)); }

__device__ float erfinv_xla(float x) {
    float w = -log1pf(-x * x);
    float p;
    if (w < 5.0f) {
        w -= 2.5f;
        p = 2.81022636e-08f;
        p = fmaf(p, w, 3.43273939e-07f);
        p = fmaf(p, w, -3.5233877e-06f);
        p = fmaf(p, w, -4.39150654e-06f);
        p = fmaf(p, w, 0.00021858087f);
        p = fmaf(p, w, -0.00125372503f);
        p = fmaf(p, w, -0.00417768164f);
        p = fmaf(p, w, 0.246640727f);
        p = fmaf(p, w, 1.50140941f);
    } else {
        w = sqrtf(w) - 3.0f;
        p = -0.000200214257f;
        p = fmaf(p, w, 0.000100950558f);
        p = fmaf(p, w, 0.00134934322f);
        p = fmaf(p, w, -0.00367342844f);
        p = fmaf(p, w, 0.00573950773f);
        p = fmaf(p, w, -0.0076224613f);
        p = fmaf(p, w, 0.00943887047f);
        p = fmaf(p, w, 1.00167406f);
        p = fmaf(p, w, 2.83297682f);
    }
    return p * x;
}

__device__ __forceinline__ float bits_to_normal(unsigned bits) {
    float f = __uint_as_float((bits >> 9) | 0x3F800000u) - 1.0f;
    const float lo = -0.99999994f;
    float u = fmaxf(lo, fmaf(f, 2.0f, lo));
    return 1.41421356f * erfinv_xla(u);
}

__global__ void threefryNormal(float* __restrict__ x0) {
    int i = threadIdx.x;  // 512 threads
    const unsigned k0 = 0u, k1 = 42u;
    const unsigned ks2 = k0 ^ k1 ^ 0x1BD11BDAu;
    unsigned x = (unsigned)i + k0;
    unsigned y = (unsigned)(i + 512) + k1;
#define TFRND(r) { x += y; y = rotl32(y, r); y ^= x; }
#define TF4A TFRND(13) TFRND(15) TFRND(26) TFRND(6)
#define TF4B TFRND(17) TFRND(29) TFRND(16) TFRND(24)
    TF4A x += k1;  y += ks2 + 1u;
    TF4B x += ks2; y += k0  + 2u;
    TF4A x += k0;  y += k1  + 3u;
    TF4B x += k1;  y += ks2 + 4u;
    TF4A x += ks2; y += k0  + 5u;
    x0[i]       = bits_to_normal(x);
    x0[i + 512] = bits_to_normal(y);
}

// ---------------- dictionary normalization ----------------
__global__ void colNorms(const float* __restrict__ W, float* __restrict__ cn) {
    int m = blockIdx.x * 256 + threadIdx.x;
    float s = 0.0f;
    for (int i = 0; i < NDIM; i++) { float v = W[i * MDIM + m]; s += v * v; }
    cn[m] = sqrtf(s);
}

__global__ void normW(const float* __restrict__ W, const float* __restrict__ cn,
                      float* __restrict__ Wn, float* __restrict__ WnT) {
    int idx = blockIdx.x * 256 + threadIdx.x;
    int i = idx >> 10, m = idx & 1023;
    float v = W[idx] / cn[m];
    Wn[idx] = v;
    WnT[m * NDIM + i] = v;
}

// ---------------- 128x64-tile SGEMM, row-major NN, register-prefetch pipeline ----------------
// MODE 0: C = A*B      MODE 1: C = Gin - eta*(A*B)
// Requires: M % 128 == 0, N % 64 == 0, K % 16 == 0.
template <int MODE>
__global__ void __launch_bounds__(256) sgemm2(
    const float* __restrict__ A, const float* __restrict__ B, float* __restrict__ C,
    int M, int N, int K,
    const float* __restrict__ etaPtr, const float* __restrict__ Gin)
{
    __shared__ float As[16][129];   // transposed A tile, pad 129 -> conflict-free scattered stores
    __shared__ float Bs[16][64];
    int t = threadIdx.x;
    int tx = t & 15, ty = t >> 4;
    int bm = blockIdx.y, bn = blockIdx.x;
    const float* Ab = A + (size_t)bm * 128 * K;
    const float* Bb = B + bn * 64;

    int arow = t >> 2;            // 0..63
    int ak   = (t & 3) * 4;       // 0,4,8,12
    int brow = t >> 4;            // 0..15
    int bcol = (t & 15) * 4;      // 0..60

    // prologue: tile 0
    {
        float4 a0 = *(const float4*)(Ab + (size_t)arow * K + ak);
        float4 a1 = *(const float4*)(Ab + (size_t)(arow + 64) * K + ak);
        float4 b0 = *(const float4*)(Bb + (size_t)brow * N + bcol);
        As[ak + 0][arow] = a0.x; As[ak + 1][arow] = a0.y;
        As[ak + 2][arow] = a0.z; As[ak + 3][arow] = a0.w;
        As[ak + 0][arow + 64] = a1.x; As[ak + 1][arow + 64] = a1.y;
        As[ak + 2][arow + 64] = a1.z; As[ak + 3][arow + 64] = a1.w;
        *(float4*)&Bs[brow][bcol] = b0;
    }
    __syncthreads();

    float acc[8][4] = {};
    int ntiles = K >> 4;
    for (int tile = 0; tile < ntiles; tile++) {
        float4 na0, na1, nb0;
        bool more = (tile + 1 < ntiles);
        if (more) {
            int kt = (tile + 1) << 4;
            na0 = *(const float4*)(Ab + (size_t)arow * K + kt + ak);
            na1 = *(const float4*)(Ab + (size_t)(arow + 64) * K + kt + ak);
            nb0 = *(const float4*)(Bb + (size_t)(kt + brow) * N + bcol);
        }
#pragma unroll
        for (int kk = 0; kk < 16; kk++) {
            float ar[8];
#pragma unroll
            for (int i = 0; i < 8; i++) ar[i] = As[kk][ty * 8 + i];
            const float4 b4 = *(const float4*)&Bs[kk][tx * 4];
#pragma unroll
            for (int i = 0; i < 8; i++) {
                acc[i][0] = fmaf(ar[i], b4.x, acc[i][0]);
                acc[i][1] = fmaf(ar[i], b4.y, acc[i][1]);
                acc[i][2] = fmaf(ar[i], b4.z, acc[i][2]);
                acc[i][3] = fmaf(ar[i], b4.w, acc[i][3]);
            }
        }
        if (more) {
            __syncthreads();
            As[ak + 0][arow] = na0.x; As[ak + 1][arow] = na0.y;
            As[ak + 2][arow] = na0.z; As[ak + 3][arow] = na0.w;
            As[ak + 0][arow + 64] = na1.x; As[ak + 1][arow + 64] = na1.y;
            As[ak + 2][arow + 64] = na1.z; As[ak + 3][arow + 64] = na1.w;
            *(float4*)&Bs[brow][bcol] = nb0;
            __syncthreads();
        }
    }

    int row0 = bm * 128 + ty * 8;
    int col0 = bn * 64 + tx * 4;
    float eta = (MODE == 1) ? *etaPtr : 0.0f;
#pragma unroll
    for (int i = 0; i < 8; i++) {
        size_t idx = (size_t)(row0 + i) * N + col0;
        float4 v;
        v.x = acc[i][0]; v.y = acc[i][1]; v.z = acc[i][2]; v.w = acc[i][3];
        if (MODE == 1) {
            float4 g = *(const float4*)(Gin + idx);
            v.x = g.x - eta * v.x; v.y = g.y - eta * v.y;
            v.z = g.z - eta * v.z; v.w = g.w - eta * v.w;
        }
        *(float4*)(C + idx) = v;
    }
}

// ---------------- matvec (1024x1024) with input renormalization ----------------
__global__ void __launch_bounds__(256) matvec(const float* __restrict__ A, const float* __restrict__ xin,
                                              const float* __restrict__ ssPrev, float* __restrict__ yout) {
    __shared__ float red[256];
    int row = blockIdx.x, t = threadIdx.x;
    const float* a = A + (size_t)row * MDIM;
    float s = 0.0f;
    for (int j = t; j < MDIM; j += 256) s = fmaf(a[j], xin[j], s);
    red[t] = s;
    __syncthreads();
    for (int off = 128; off; off >>= 1) { if (t < off) red[t] += red[t + off]; __syncthreads(); }
    if (t == 0) {
        float scale = ssPrev ? (1.0f / sqrtf(*ssPrev)) : 1.0f;
        yout[row] = red[0] * scale;
    }
}

__global__ void sumsq1024(const float* __restrict__ v, float* __restrict__ out) {
    __shared__ float red[256];
    int t = threadIdx.x;
    float s = 0.0f;
    for (int j = t; j < MDIM; j += 256) { float x = v[j]; s += x * x; }
    red[t] = s;
    __syncthreads();
    for (int off = 128; off; off >>= 1) { if (t < off) red[t] += red[t + off]; __syncthreads(); }
    if (t == 0) *out = red[0];
}

__global__ void computeEta(const float* __restrict__ ssLast, float* __restrict__ eta) {
    *eta = 1.0f / sqrtf(*ssLast);
}

__global__ void ynormPart(const float* __restrict__ Y, float* __restrict__ part) {
    __shared__ float red[256];
    int t = threadIdx.x;
    size_t base = (size_t)blockIdx.x * 4096;
    float s = 0.0f;
    for (int j = t; j < 4096; j += 256) { float x = Y[base + j]; s += x * x; }
    red[t] = s;
    __syncthreads();
    for (int off = 128; off; off >>= 1) { if (t < off) red[t] += red[t + off]; __syncthreads(); }
    if (t == 0) part[blockIdx.x] = red[0];
}

__global__ void zeroBuf(float* __restrict__ p, int n) {
    int i = blockIdx.x * 256 + threadIdx.x;
    if (i < n) p[i] = 0.0f;
}
__global__ void negCopy(const float* __restrict__ src, float* __restrict__ dst, int n) {
    int i = blockIdx.x * 256 + threadIdx.x;
    if (i < n) dst[i] = -src[i];
}

// ---------------- fused: exact top-K threshold + sparse-compact + Resid = Gamma@WnT - Y ----------------
// One block per row. 256 threads, each owning 4 contiguous Gtmp values in registers.
// 1) 4-pass radix select of the 65th-largest |g| (bit pattern 'prefix')
// 2) ordered compaction of kept (idx,val) pairs into smem (deterministic)
// 3) dense Gamma row write
// 4) Resid row = sum_k val_k * WnT[idx_k,:] - Y[row,:]  (ascending idx order == dense fp order)
__global__ void __launch_bounds__(256) fusedHT(
    const float* __restrict__ Gtmp, float* __restrict__ Gamma,
    const float* __restrict__ WnT, const float* __restrict__ Y,
    float* __restrict__ Resid, float* __restrict__ partial)
{
    __shared__ int   hist[256];
    __shared__ int   sA[256];
    __shared__ int   sB[256];
    __shared__ float sval[KSP];
    __shared__ int   sidx[KSP];
    __shared__ int   s_sel, s_above, s_total;
    __shared__ float red[256];

    int row = blockIdx.x, t = threadIdx.x;
    const float4 g4 = *(const float4*)(Gtmp + ((size_t)row << 10) + (t << 2));
    unsigned k0 = __float_as_uint(g4.x) & 0x7FFFFFFFu;
    unsigned k1 = __float_as_uint(g4.y) & 0x7FFFFFFFu;
    unsigned k2 = __float_as_uint(g4.z) & 0x7FFFFFFFu;
    unsigned k3 = __float_as_uint(g4.w) & 0x7FFFFFFFu;

    unsigned prefix = 0, mask = 0;
    int r = KSP;   // 0-based descending rank 64 == 65th largest
    for (int p = 0; p < 4; p++) {
        int sh = 24 - 8 * p;
        hist[t] = 0;
        __syncthreads();
        if ((k0 & mask) == prefix) atomicAdd(&hist[(k0 >> sh) & 0xFF], 1);
        if ((k1 & mask) == prefix) atomicAdd(&hist[(k1 >> sh) & 0xFF], 1);
        if ((k2 & mask) == prefix) atomicAdd(&hist[(k2 >> sh) & 0xFF], 1);
        if ((k3 & mask) == prefix) atomicAdd(&hist[(k3 >> sh) & 0xFF], 1);
        __syncthreads();
        sA[t] = hist[t];
        __syncthreads();
        int* src = sA; int* dst = sB;
        for (int off = 1; off < 256; off <<= 1) {
            int v = src[t] + ((t + off < 256) ? src[t + off] : 0);  // inclusive suffix sum
            dst[t] = v;
            __syncthreads();
            int* tmp = src; src = dst; dst = tmp;
        }
        int above = (t < 255) ? src[t + 1] : 0;   // strictly-above count
        if (hist[t] > 0 && above <= r && r < above + hist[t]) { s_sel = t; s_above = above; }
        __syncthreads();
        prefix |= ((unsigned)s_sel) << sh;
        mask   |= 0xFFu << sh;
        r -= s_above;
        __syncthreads();
    }

    // ordered compaction
    int f0 = (k0 > prefix), f1 = (k1 > prefix), f2 = (k2 > prefix), f3 = (k3 > prefix);
    int lc = f0 + f1 + f2 + f3;
    sA[t] = lc;
    __syncthreads();
    {
        int* src = sA; int* dst = sB;
        for (int off = 1; off < 256; off <<= 1) {
            int v = src[t] + ((t >= off) ? src[t - off] : 0);  // inclusive prefix sum
            dst[t] = v;
            __syncthreads();
            int* tmp = src; src = dst; dst = tmp;
        }
        int incl = src[t];
        if (t == 255) s_total = incl;
        int pos = incl - lc;
        if (f0) { sidx[pos] = 4 * t + 0; sval[pos] = g4.x; pos++; }
        if (f1) { sidx[pos] = 4 * t + 1; sval[pos] = g4.y; pos++; }
        if (f2) { sidx[pos] = 4 * t + 2; sval[pos] = g4.z; pos++; }
        if (f3) { sidx[pos] = 4 * t + 3; sval[pos] = g4.w; pos++; }
    }
    // dense Gamma row
    {
        float4 go;
        go.x = f0 ? g4.x : 0.0f;
        go.y = f1 ? g4.y : 0.0f;
        go.z = f2 ? g4.z : 0.0f;
        go.w = f3 ? g4.w : 0.0f;
        *(float4*)(Gamma + ((size_t)row << 10) + (t << 2)) = go;
    }
    __syncthreads();
    int cntT = s_total;   // <= 64 by construction

    // sparse residual: each thread handles 2 columns
    int c2 = t << 1;
    float ax = 0.0f, ay = 0.0f;
    int k = 0;
    for (; k + 4 <= cntT; k += 4) {
        float v0 = sval[k], v1 = sval[k + 1], v2 = sval[k + 2], v3 = sval[k + 3];
        int   i0 = sidx[k], i1 = sidx[k + 1], i2 = sidx[k + 2], i3 = sidx[k + 3];
        float2 w0 = *(const float2*)(WnT + ((size_t)i0 << 9) + c2);
        float2 w1 = *(const float2*)(WnT + ((size_t)i1 << 9) + c2);
        float2 w2 = *(const float2*)(WnT + ((size_t)i2 << 9) + c2);
        float2 w3 = *(const float2*)(WnT + ((size_t)i3 << 9) + c2);
        ax = fmaf(v0, w0.x, ax); ay = fmaf(v0, w0.y, ay);
        ax = fmaf(v1, w1.x, ax); ay = fmaf(v1, w1.y, ay);
        ax = fmaf(v2, w2.x, ax); ay = fmaf(v2, w2.y, ay);
        ax = fmaf(v3, w3.x, ax); ay = fmaf(v3, w3.y, ay);
    }
    for (; k < cntT; k++) {
        float v = sval[k]; int i = sidx[k];
        float2 w = *(const float2*)(WnT + ((size_t)i << 9) + c2);
        ax = fmaf(v, w.x, ax); ay = fmaf(v, w.y, ay);
    }
    float2 yv = *(const float2*)(Y + ((size_t)row << 9) + c2);
    float rx = ax - yv.x, ry = ay - yv.y;
    float2 ro; ro.x = rx; ro.y = ry;
    *(float2*)(Resid + ((size_t)row << 9) + c2) = ro;

    red[t] = rx * rx + ry * ry;
    __syncthreads();
    for (int off = 128; off; off >>= 1) { if (t < off) red[t] += red[t + off]; __syncthreads(); }
    if (t == 0) partial[row] = red[0];
}

// ---------------- final norms: out[b] = sqrt(sum resPart[(b+1)*1024..])/||Y|| ----------------
__global__ void __launch_bounds__(256) normsFinal2(const float* __restrict__ resPart,
                                                   const float* __restrict__ ynPart,
                                                   float* __restrict__ out) {
    __shared__ float red[256];
    __shared__ float s_rs;
    int b = blockIdx.x, t = threadIdx.x;
    const float* p = resPart + ((size_t)(b + 1) << 10);
    red[t] = p[t] + p[t + 256] + p[t + 512] + p[t + 768];
    __syncthreads();
    for (int off = 128; off; off >>= 1) { if (t < off) red[t] += red[t + off]; __syncthreads(); }
    if (t == 0) s_rs = red[0];
    __syncthreads();
    red[t] = (t < 128) ? ynPart[t] : 0.0f;
    __syncthreads();
    for (int off = 128; off; off >>= 1) { if (t < off) red[t] += red[t + off]; __syncthreads(); }
    if (t == 0) out[b] = sqrtf(s_rs) / sqrtf(red[0]);
}

// ---------------- host orchestration ----------------
extern "C" void kernel_launch(void* const* d_in, const int* in_sizes, int n_in,
                              void* d_out, int out_size) {
    (void)in_sizes; (void)n_in; (void)out_size;
    const float* Y = (const float*)d_in[0];  // [1024,512]
    const float* W = (const float*)d_in[1];  // [512,1024]
    float* out = (float*)d_out;

    float *Wn, *WnT, *G, *P1, *P2, *Gamma, *Gtmp, *Resid, *x0, *vA, *vB, *ss, *cn, *eta, *ynP, *rsP;
    cudaGetSymbolAddress((void**)&Wn, d_Wn);
    cudaGetSymbolAddress((void**)&WnT, d_WnT);
    cudaGetSymbolAddress((void**)&G, d_G);
    cudaGetSymbolAddress((void**)&P1, d_P1);
    cudaGetSymbolAddress((void**)&P2, d_P2);
    cudaGetSymbolAddress((void**)&Gamma, d_Gamma);
    cudaGetSymbolAddress((void**)&Gtmp, d_Gtmp);
    cudaGetSymbolAddress((void**)&Resid, d_Resid);
    cudaGetSymbolAddress((void**)&x0, d_x0);
    cudaGetSymbolAddress((void**)&vA, d_vA);
    cudaGetSymbolAddress((void**)&vB, d_vB);
    cudaGetSymbolAddress((void**)&ss, d_ss);
    cudaGetSymbolAddress((void**)&cn, d_cn);
    cudaGetSymbolAddress((void**)&eta, d_eta);
    cudaGetSymbolAddress((void**)&ynP, d_ynPart);
    cudaGetSymbolAddress((void**)&rsP, d_resPart);

    // 1) dictionary normalization
    colNorms<<<4, 256>>>(W, cn);
    normW<<<2048, 256>>>(W, cn, Wn, WnT);

    // 2) power method: exact jax x0; G = Wn^T Wn; repeated squaring to G^16
    threefryNormal<<<1, 512>>>(x0);
    sgemm2<0><<<dim3(16, 8), 256>>>(WnT, Wn, G, MDIM, MDIM, NDIM, nullptr, nullptr);
    sgemm2<0><<<dim3(16, 8), 256>>>(G,  G,  P1, MDIM, MDIM, MDIM, nullptr, nullptr);  // G^2
    sgemm2<0><<<dim3(16, 8), 256>>>(P1, P1, P2, MDIM, MDIM, MDIM, nullptr, nullptr);  // G^4
    sgemm2<0><<<dim3(16, 8), 256>>>(P2, P2, P1, MDIM, MDIM, MDIM, nullptr, nullptr);  // G^8
    sgemm2<0><<<dim3(16, 8), 256>>>(P1, P1, P2, MDIM, MDIM, MDIM, nullptr, nullptr);  // G^16

    // 3) matvec chain: 3x G, 6x G^16, 1x G (=100 applications), renormalize each step
    matvec<<<MDIM, 256>>>(G, x0, nullptr, vA);   sumsq1024<<<1, 256>>>(vA, ss + 0);
    matvec<<<MDIM, 256>>>(G, vA, ss + 0, vB);    sumsq1024<<<1, 256>>>(vB, ss + 1);
    matvec<<<MDIM, 256>>>(G, vB, ss + 1, vA);    sumsq1024<<<1, 256>>>(vA, ss + 2);
    matvec<<<MDIM, 256>>>(P2, vA, ss + 2, vB);   sumsq1024<<<1, 256>>>(vB, ss + 3);
    matvec<<<MDIM, 256>>>(P2, vB, ss + 3, vA);   sumsq1024<<<1, 256>>>(vA, ss + 4);
    matvec<<<MDIM, 256>>>(P2, vA, ss + 4, vB);   sumsq1024<<<1, 256>>>(vB, ss + 5);
    matvec<<<MDIM, 256>>>(P2, vB, ss + 5, vA);   sumsq1024<<<1, 256>>>(vA, ss + 6);
    matvec<<<MDIM, 256>>>(P2, vA, ss + 6, vB);   sumsq1024<<<1, 256>>>(vB, ss + 7);
    matvec<<<MDIM, 256>>>(P2, vB, ss + 7, vA);   sumsq1024<<<1, 256>>>(vA, ss + 8);
    matvec<<<MDIM, 256>>>(G,  vA, ss + 8, vB);   sumsq1024<<<1, 256>>>(vB, ss + 9);
    computeEta<<<1, 1>>>(ss + 9, eta);

    // 4) ||Y|| partials
    ynormPart<<<128, 256>>>(Y, ynP);

    // 5) IHT: Gamma=0, residual=-Y, then 51 uniform iterations of 2 kernels
    zeroBuf<<<4096, 256>>>(Gamma, BDIM * MDIM);
    negCopy<<<2048, 256>>>(Y, Resid, BDIM * NDIM);

    for (int t = 0; t < NITER; t++) {
        // Gtmp = Gamma - eta * (Resid @ Wn)   [1024,1024], K=512
        sgemm2<1><<<dim3(16, 8), 256>>>(Resid, Wn, Gtmp, BDIM, MDIM, NDIM, eta, Gamma);
        // Gamma = HT_K(Gtmp); Resid = Gamma @ Wn^T - Y; norm partial
        fusedHT<<<BDIM, 256>>>(Gtmp, Gamma, WnT, Y, Resid, rsP + (size_t)t * BDIM);
    }

    // 6) outputs: X = Wn @ Gamma [512,1024], Gamma [1024,1024], norms [50]
    sgemm2<0><<<dim3(16, 4), 256>>>(Wn, Gamma, out, NDIM, MDIM, MDIM, nullptr, nullptr);
    cudaMemcpyAsync(out + NDIM * MDIM, Gamma, (size_t)BDIM * MDIM * sizeof(float),
                    cudaMemcpyDeviceToDevice);
    normsFinal2<<<50, 256>>>(rsP, ynP, out + NDIM * MDIM + BDIM * MDIM);
}

// round 12
// speedup vs baseline: 2.3556x; 1.0175x over previous
#include <cuda_runtime.h>
#include <stdint.h>
#include <math.h>

// Problem constants: N=512, M=1024, B=1024, K=64, 100 power iters, 50 IHT iters
#define NDIM 512
#define MDIM 1024
#define BDIM 1024
#define KSP  64
#define NITER 51  // init + 50

// ---------------- static device scratch ----------------
__device__ float d_Wn   [NDIM * MDIM];
__device__ float d_WnT  [MDIM * NDIM];
__device__ float d_G    [MDIM * MDIM];
__device__ float d_P1   [MDIM * MDIM];
__device__ float d_P2   [MDIM * MDIM];
__device__ float d_Gamma[BDIM * MDIM];
__device__ float d_Gtmp [BDIM * MDIM];
__device__ float d_Resid[BDIM * NDIM];
__device__ float d_x0[MDIM];
__device__ float d_vA[MDIM];
__device__ float d_vB[MDIM];
__device__ float d_ss[16];
__device__ float d_cn[MDIM];
__device__ float d_eta[1];
__device__ float d_ynPart[128];
__device__ float d_resPart[NITER * BDIM];

// ---------------- f32x2 packed helpers ----------------
__device__ __forceinline__ unsigned long long pack2(float lo, float hi) {
    unsigned long long r;
    asm("mov.b64 %0, {%1, %2};" : "=l"(r) : "f"(lo), "f"(hi));
    return r;
}
__device__ __forceinline__ void fma2(unsigned long long& d, unsigned long long a, unsigned long long b) {
    asm("fma.rn.f32x2 %0, %1, %2, %0;" : "+l"(d) : "l"(a), "l"(b));
}
__device__ __forceinline__ void unpack2(unsigned long long v, float& lo, float& hi) {
    asm("mov.b64 {%0, %1}, %2;" : "=f"(lo), "=f"(hi) : "l"(v));
}

// ---------------- threefry + XLA erf_inv (jax.random.normal(key(42),(1,1024))) ----------------
__device__ __forceinline__ unsigned rotl32(unsigned x, int d) { return (x << d) | (x >> (32 - d)); }

__device__ float erfinv_xla(float x) {
    float w = -log1pf(-x * x);
    float p;
    if (w < 5.0f) {
        w -= 2.5f;
        p = 2.81022636e-08f;
        p = fmaf(p, w, 3.43273939e-07f);
        p = fmaf(p, w, -3.5233877e-06f);
        p = fmaf(p, w, -4.39150654e-06f);
        p = fmaf(p, w, 0.00021858087f);
        p = fmaf(p, w, -0.00125372503f);
        p = fmaf(p, w, -0.00417768164f);
        p = fmaf(p, w, 0.246640727f);
        p = fmaf(p, w, 1.50140941f);
    } else {
        w = sqrtf(w) - 3.0f;
        p = -0.000200214257f;
        p = fmaf(p, w, 0.000100950558f);
        p = fmaf(p, w, 0.00134934322f);
        p = fmaf(p, w, -0.00367342844f);
        p = fmaf(p, w, 0.00573950773f);
        p = fmaf(p, w, -0.0076224613f);
        p = fmaf(p, w, 0.00943887047f);
        p = fmaf(p, w, 1.00167406f);
        p = fmaf(p, w, 2.83297682f);
    }
    return p * x;
}

__device__ __forceinline__ float bits_to_normal(unsigned bits) {
    float f = __uint_as_float((bits >> 9) | 0x3F800000u) - 1.0f;
    const float lo = -0.99999994f;
    float u = fmaxf(lo, fmaf(f, 2.0f, lo));
    return 1.41421356f * erfinv_xla(u);
}

__global__ void threefryNormal(float* __restrict__ x0) {
    int i = threadIdx.x;  // 512 threads
    const unsigned k0 = 0u, k1 = 42u;
    const unsigned ks2 = k0 ^ k1 ^ 0x1BD11BDAu;
    unsigned x = (unsigned)i + k0;
    unsigned y = (unsigned)(i + 512) + k1;
#define TFRND(r) { x += y; y = rotl32(y, r); y ^= x; }
#define TF4A TFRND(13) TFRND(15) TFRND(26) TFRND(6)
#define TF4B TFRND(17) TFRND(29) TFRND(16) TFRND(24)
    TF4A x += k1;  y += ks2 + 1u;
    TF4B x += ks2; y += k0  + 2u;
    TF4A x += k0;  y += k1  + 3u;
    TF4B x += k1;  y += ks2 + 4u;
    TF4A x += ks2; y += k0  + 5u;
    x0[i]       = bits_to_normal(x);
    x0[i + 512] = bits_to_normal(y);
}

// ---------------- dictionary normalization ----------------
__global__ void colNorms(const float* __restrict__ W, float* __restrict__ cn) {
    int m = blockIdx.x * 256 + threadIdx.x;
    float s = 0.0f;
    for (int i = 0; i < NDIM; i++) { float v = W[i * MDIM + m]; s += v * v; }
    cn[m] = sqrtf(s);
}

__global__ void normW(const float* __restrict__ W, const float* __restrict__ cn,
                      float* __restrict__ Wn, float* __restrict__ WnT) {
    int idx = blockIdx.x * 256 + threadIdx.x;
    int i = idx >> 10, m = idx & 1023;
    float v = W[idx] / cn[m];
    Wn[idx] = v;
    WnT[m * NDIM + i] = v;
}

// ---------------- 128x64-tile SGEMM, f32x2 FFMA2, double-buffered smem ----------------
// MODE 0: C = A*B      MODE 1: C = Gin - eta*(A*B)
// Requires: M % 128 == 0, N % 64 == 0, K % 16 == 0.
// Per-output accumulation is ascending in k with scalar-rn semantics (f32x2 lanes are
// independent rn fp32 FMAs) -> results bitwise-identical to the round-9 kernel.
template <int MODE>
__global__ void __launch_bounds__(256) sgemm3(
    const float* __restrict__ A, const float* __restrict__ B, float* __restrict__ C,
    int M, int N, int K,
    const float* __restrict__ etaPtr, const float* __restrict__ Gin)
{
    __shared__ float As[2][16][132];   // row stride 528B: 16B-aligned, bank-spread
    __shared__ float Bs[2][16][64];
    int t = threadIdx.x;
    int tx = t & 15, ty = t >> 4;
    int bm = blockIdx.y, bn = blockIdx.x;
    const float* Ab = A + (size_t)bm * 128 * K;
    const float* Bb = B + bn * 64;

    int arow = t >> 2;            // 0..63
    int ak   = (t & 3) * 4;       // 0,4,8,12
    int brow = t >> 4;            // 0..15
    int bcol = (t & 15) * 4;      // 0..60

    // prologue: tile 0 -> buffer 0
    {
        float4 a0 = *(const float4*)(Ab + (size_t)arow * K + ak);
        float4 a1 = *(const float4*)(Ab + (size_t)(arow + 64) * K + ak);
        float4 b0 = *(const float4*)(Bb + (size_t)brow * N + bcol);
        As[0][ak + 0][arow] = a0.x; As[0][ak + 1][arow] = a0.y;
        As[0][ak + 2][arow] = a0.z; As[0][ak + 3][arow] = a0.w;
        As[0][ak + 0][arow + 64] = a1.x; As[0][ak + 1][arow + 64] = a1.y;
        As[0][ak + 2][arow + 64] = a1.z; As[0][ak + 3][arow + 64] = a1.w;
        *(float4*)&Bs[0][brow][bcol] = b0;
    }
    __syncthreads();

    unsigned long long acc2[8][2];
#pragma unroll
    for (int i = 0; i < 8; i++) { acc2[i][0] = 0ull; acc2[i][1] = 0ull; }

    int ntiles = K >> 4;
    for (int tile = 0; tile < ntiles; tile++) {
        int cur = tile & 1;
        float4 na0, na1, nb0;
        bool more = (tile + 1 < ntiles);
        if (more) {
            int kt = (tile + 1) << 4;
            na0 = *(const float4*)(Ab + (size_t)arow * K + kt + ak);
            na1 = *(const float4*)(Ab + (size_t)(arow + 64) * K + kt + ak);
            nb0 = *(const float4*)(Bb + (size_t)(kt + brow) * N + bcol);
        }
#pragma unroll
        for (int kk = 0; kk < 16; kk++) {
            float4 a0 = *(const float4*)&As[cur][kk][ty * 8];
            float4 a1 = *(const float4*)&As[cur][kk][ty * 8 + 4];
            float4 b  = *(const float4*)&Bs[cur][kk][tx * 4];
            unsigned long long b01 = pack2(b.x, b.y);
            unsigned long long b23 = pack2(b.z, b.w);
            float av[8] = {a0.x, a0.y, a0.z, a0.w, a1.x, a1.y, a1.z, a1.w};
#pragma unroll
            for (int i = 0; i < 8; i++) {
                unsigned long long ap = pack2(av[i], av[i]);
                fma2(acc2[i][0], ap, b01);
                fma2(acc2[i][1], ap, b23);
            }
        }
        if (more) {
            int nxt = cur ^ 1;
            As[nxt][ak + 0][arow] = na0.x; As[nxt][ak + 1][arow] = na0.y;
            As[nxt][ak + 2][arow] = na0.z; As[nxt][ak + 3][arow] = na0.w;
            As[nxt][ak + 0][arow + 64] = na1.x; As[nxt][ak + 1][arow + 64] = na1.y;
            As[nxt][ak + 2][arow + 64] = na1.z; As[nxt][ak + 3][arow + 64] = na1.w;
            *(float4*)&Bs[nxt][brow][bcol] = nb0;
        }
        __syncthreads();
    }

    int row0 = bm * 128 + ty * 8;
    int col0 = bn * 64 + tx * 4;
    float eta = (MODE == 1) ? *etaPtr : 0.0f;
#pragma unroll
    for (int i = 0; i < 8; i++) {
        size_t idx = (size_t)(row0 + i) * N + col0;
        float4 v;
        unpack2(acc2[i][0], v.x, v.y);
        unpack2(acc2[i][1], v.z, v.w);
        if (MODE == 1) {
            float4 g = *(const float4*)(Gin + idx);
            v.x = g.x - eta * v.x; v.y = g.y - eta * v.y;
            v.z = g.z - eta * v.z; v.w = g.w - eta * v.w;
        }
        *(float4*)(C + idx) = v;
    }
}

// ---------------- matvec (1024x1024) with input renormalization ----------------
__global__ void __launch_bounds__(256) matvec(const float* __restrict__ A, const float* __restrict__ xin,
                                              const float* __restrict__ ssPrev, float* __restrict__ yout) {
    __shared__ float red[256];
    int row = blockIdx.x, t = threadIdx.x;
    const float* a = A + (size_t)row * MDIM;
    float s = 0.0f;
    for (int j = t; j < MDIM; j += 256) s = fmaf(a[j], xin[j], s);
    red[t] = s;
    __syncthreads();
    for (int off = 128; off; off >>= 1) { if (t < off) red[t] += red[t + off]; __syncthreads(); }
    if (t == 0) {
        float scale = ssPrev ? (1.0f / sqrtf(*ssPrev)) : 1.0f;
        yout[row] = red[0] * scale;
    }
}

__global__ void sumsq1024(const float* __restrict__ v, float* __restrict__ out) {
    __shared__ float red[256];
    int t = threadIdx.x;
    float s = 0.0f;
    for (int j = t; j < MDIM; j += 256) { float x = v[j]; s += x * x; }
    red[t] = s;
    __syncthreads();
    for (int off = 128; off; off >>= 1) { if (t < off) red[t] += red[t + off]; __syncthreads(); }
    if (t == 0) *out = red[0];
}

__global__ void computeEta(const float* __restrict__ ssLast, float* __restrict__ eta) {
    *eta = 1.0f / sqrtf(*ssLast);
}

__global__ void ynormPart(const float* __restrict__ Y, float* __restrict__ part) {
    __shared__ float red[256];
    int t = threadIdx.x;
    size_t base = (size_t)blockIdx.x * 4096;
    float s = 0.0f;
    for (int j = t; j < 4096; j += 256) { float x = Y[base + j]; s += x * x; }
    red[t] = s;
    __syncthreads();
    for (int off = 128; off; off >>= 1) { if (t < off) red[t] += red[t + off]; __syncthreads(); }
    if (t == 0) part[blockIdx.x] = red[0];
}

__global__ void zeroBuf(float* __restrict__ p, int n) {
    int i = blockIdx.x * 256 + threadIdx.x;
    if (i < n) p[i] = 0.0f;
}
__global__ void negCopy(const float* __restrict__ src, float* __restrict__ dst, int n) {
    int i = blockIdx.x * 256 + threadIdx.x;
    if (i < n) dst[i] = -src[i];
}

// ---------------- fused: exact top-K threshold + sparse Resid = Gamma@WnT - Y ----------------
__global__ void __launch_bounds__(256) fusedHT(
    const float* __restrict__ Gtmp, float* __restrict__ Gamma,
    const float* __restrict__ WnT, const float* __restrict__ Y,
    float* __restrict__ Resid, float* __restrict__ partial)
{
    __shared__ int   hist[256];
    __shared__ int   sA[256];
    __shared__ int   sB[256];
    __shared__ float sval[KSP];
    __shared__ int   sidx[KSP];
    __shared__ int   s_sel, s_above, s_total;
    __shared__ float red[256];

    int row = blockIdx.x, t = threadIdx.x;
    const float4 g4 = *(const float4*)(Gtmp + ((size_t)row << 10) + (t << 2));
    unsigned k0 = __float_as_uint(g4.x) & 0x7FFFFFFFu;
    unsigned k1 = __float_as_uint(g4.y) & 0x7FFFFFFFu;
    unsigned k2 = __float_as_uint(g4.z) & 0x7FFFFFFFu;
    unsigned k3 = __float_as_uint(g4.w) & 0x7FFFFFFFu;

    unsigned prefix = 0, mask = 0;
    int r = KSP;   // 0-based descending rank 64 == 65th largest
    for (int p = 0; p < 4; p++) {
        int sh = 24 - 8 * p;
        hist[t] = 0;
        __syncthreads();
        if ((k0 & mask) == prefix) atomicAdd(&hist[(k0 >> sh) & 0xFF], 1);
        if ((k1 & mask) == prefix) atomicAdd(&hist[(k1 >> sh) & 0xFF], 1);
        if ((k2 & mask) == prefix) atomicAdd(&hist[(k2 >> sh) & 0xFF], 1);
        if ((k3 & mask) == prefix) atomicAdd(&hist[(k3 >> sh) & 0xFF], 1);
        __syncthreads();
        sA[t] = hist[t];
        __syncthreads();
        int* src = sA; int* dst = sB;
        for (int off = 1; off < 256; off <<= 1) {
            int v = src[t] + ((t + off < 256) ? src[t + off] : 0);  // inclusive suffix sum
            dst[t] = v;
            __syncthreads();
            int* tmp = src; src = dst; dst = tmp;
        }
        int above = (t < 255) ? src[t + 1] : 0;   // strictly-above count
        if (hist[t] > 0 && above <= r && r < above + hist[t]) { s_sel = t; s_above = above; }
        __syncthreads();
        prefix |= ((unsigned)s_sel) << sh;
        mask   |= 0xFFu << sh;
        r -= s_above;
        __syncthreads();
    }

    // ordered compaction
    int f0 = (k0 > prefix), f1 = (k1 > prefix), f2 = (k2 > prefix), f3 = (k3 > prefix);
    int lc = f0 + f1 + f2 + f3;
    sA[t] = lc;
    __syncthreads();
    {
        int* src = sA; int* dst = sB;
        for (int off = 1; off < 256; off <<= 1) {
            int v = src[t] + ((t >= off) ? src[t - off] : 0);  // inclusive prefix sum
            dst[t] = v;
            __syncthreads();
            int* tmp = src; src = dst; dst = tmp;
        }
        int incl = src[t];
        if (t == 255) s_total = incl;
        int pos = incl - lc;
        if (f0) { sidx[pos] = 4 * t + 0; sval[pos] = g4.x; pos++; }
        if (f1) { sidx[pos] = 4 * t + 1; sval[pos] = g4.y; pos++; }
        if (f2) { sidx[pos] = 4 * t + 2; sval[pos] = g4.z; pos++; }
        if (f3) { sidx[pos] = 4 * t + 3; sval[pos] = g4.w; pos++; }
    }
    // dense Gamma row
    {
        float4 go;
        go.x = f0 ? g4.x : 0.0f;
        go.y = f1 ? g4.y : 0.0f;
        go.z = f2 ? g4.z : 0.0f;
        go.w = f3 ? g4.w : 0.0f;
        *(float4*)(Gamma + ((size_t)row << 10) + (t << 2)) = go;
    }
    __syncthreads();
    int cntT = s_total;   // <= 64 by construction

    // sparse residual: each thread handles 2 columns
    int c2 = t << 1;
    float ax = 0.0f, ay = 0.0f;
    int k = 0;
    for (; k + 4 <= cntT; k += 4) {
        float v0 = sval[k], v1 = sval[k + 1], v2 = sval[k + 2], v3 = sval[k + 3];
        int   i0 = sidx[k], i1 = sidx[k + 1], i2 = sidx[k + 2], i3 = sidx[k + 3];
        float2 w0 = *(const float2*)(WnT + ((size_t)i0 << 9) + c2);
        float2 w1 = *(const float2*)(WnT + ((size_t)i1 << 9) + c2);
        float2 w2 = *(const float2*)(WnT + ((size_t)i2 << 9) + c2);
        float2 w3 = *(const float2*)(WnT + ((size_t)i3 << 9) + c2);
        ax = fmaf(v0, w0.x, ax); ay = fmaf(v0, w0.y, ay);
        ax = fmaf(v1, w1.x, ax); ay = fmaf(v1, w1.y, ay);
        ax = fmaf(v2, w2.x, ax); ay = fmaf(v2, w2.y, ay);
        ax = fmaf(v3, w3.x, ax); ay = fmaf(v3, w3.y, ay);
    }
    for (; k < cntT; k++) {
        float v = sval[k]; int i = sidx[k];
        float2 w = *(const float2*)(WnT + ((size_t)i << 9) + c2);
        ax = fmaf(v, w.x, ax); ay = fmaf(v, w.y, ay);
    }
    float2 yv = *(const float2*)(Y + ((size_t)row << 9) + c2);
    float rx = ax - yv.x, ry = ay - yv.y;
    float2 ro; ro.x = rx; ro.y = ry;
    *(float2*)(Resid + ((size_t)row << 9) + c2) = ro;

    red[t] = rx * rx + ry * ry;
    __syncthreads();
    for (int off = 128; off; off >>= 1) { if (t < off) red[t] += red[t + off]; __syncthreads(); }
    if (t == 0) partial[row] = red[0];
}

// ---------------- final norms ----------------
__global__ void __launch_bounds__(256) normsFinal2(const float* __restrict__ resPart,
                                                   const float* __restrict__ ynPart,
                                                   float* __restrict__ out) {
    __shared__ float red[256];
    __shared__ float s_rs;
    int b = blockIdx.x, t = threadIdx.x;
    const float* p = resPart + ((size_t)(b + 1) << 10);
    red[t] = p[t] + p[t + 256] + p[t + 512] + p[t + 768];
    __syncthreads();
    for (int off = 128; off; off >>= 1) { if (t < off) red[t] += red[t + off]; __syncthreads(); }
    if (t == 0) s_rs = red[0];
    __syncthreads();
    red[t] = (t < 128) ? ynPart[t] : 0.0f;
    __syncthreads();
    for (int off = 128; off; off >>= 1) { if (t < off) red[t] += red[t + off]; __syncthreads(); }
    if (t == 0) out[b] = sqrtf(s_rs) / sqrtf(red[0]);
}

// ---------------- host orchestration ----------------
extern "C" void kernel_launch(void* const* d_in, const int* in_sizes, int n_in,
                              void* d_out, int out_size) {
    (void)in_sizes; (void)n_in; (void)out_size;
    const float* Y = (const float*)d_in[0];  // [1024,512]
    const float* W = (const float*)d_in[1];  // [512,1024]
    float* out = (float*)d_out;

    float *Wn, *WnT, *G, *P1, *P2, *Gamma, *Gtmp, *Resid, *x0, *vA, *vB, *ss, *cn, *eta, *ynP, *rsP;
    cudaGetSymbolAddress((void**)&Wn, d_Wn);
    cudaGetSymbolAddress((void**)&WnT, d_WnT);
    cudaGetSymbolAddress((void**)&G, d_G);
    cudaGetSymbolAddress((void**)&P1, d_P1);
    cudaGetSymbolAddress((void**)&P2, d_P2);
    cudaGetSymbolAddress((void**)&Gamma, d_Gamma);
    cudaGetSymbolAddress((void**)&Gtmp, d_Gtmp);
    cudaGetSymbolAddress((void**)&Resid, d_Resid);
    cudaGetSymbolAddress((void**)&x0, d_x0);
    cudaGetSymbolAddress((void**)&vA, d_vA);
    cudaGetSymbolAddress((void**)&vB, d_vB);
    cudaGetSymbolAddress((void**)&ss, d_ss);
    cudaGetSymbolAddress((void**)&cn, d_cn);
    cudaGetSymbolAddress((void**)&eta, d_eta);
    cudaGetSymbolAddress((void**)&ynP, d_ynPart);
    cudaGetSymbolAddress((void**)&rsP, d_resPart);

    // 1) dictionary normalization
    colNorms<<<4, 256>>>(W, cn);
    normW<<<2048, 256>>>(W, cn, Wn, WnT);

    // 2) power method: exact jax x0; G = Wn^T Wn; repeated squaring to G^16
    threefryNormal<<<1, 512>>>(x0);
    sgemm3<0><<<dim3(16, 8), 256>>>(WnT, Wn, G, MDIM, MDIM, NDIM, nullptr, nullptr);
    sgemm3<0><<<dim3(16, 8), 256>>>(G,  G,  P1, MDIM, MDIM, MDIM, nullptr, nullptr);  // G^2
    sgemm3<0><<<dim3(16, 8), 256>>>(P1, P1, P2, MDIM, MDIM, MDIM, nullptr, nullptr);  // G^4
    sgemm3<0><<<dim3(16, 8), 256>>>(P2, P2, P1, MDIM, MDIM, MDIM, nullptr, nullptr);  // G^8
    sgemm3<0><<<dim3(16, 8), 256>>>(P1, P1, P2, MDIM, MDIM, MDIM, nullptr, nullptr);  // G^16

    // 3) matvec chain: 3x G, 6x G^16, 1x G (=100 applications), renormalize each step
    matvec<<<MDIM, 256>>>(G, x0, nullptr, vA);   sumsq1024<<<1, 256>>>(vA, ss + 0);
    matvec<<<MDIM, 256>>>(G, vA, ss + 0, vB);    sumsq1024<<<1, 256>>>(vB, ss + 1);
    matvec<<<MDIM, 256>>>(G, vB, ss + 1, vA);    sumsq1024<<<1, 256>>>(vA, ss + 2);
    matvec<<<MDIM, 256>>>(P2, vA, ss + 2, vB);   sumsq1024<<<1, 256>>>(vB, ss + 3);
    matvec<<<MDIM, 256>>>(P2, vB, ss + 3, vA);   sumsq1024<<<1, 256>>>(vA, ss + 4);
    matvec<<<MDIM, 256>>>(P2, vA, ss + 4, vB);   sumsq1024<<<1, 256>>>(vB, ss + 5);
    matvec<<<MDIM, 256>>>(P2, vB, ss + 5, vA);   sumsq1024<<<1, 256>>>(vA, ss + 6);
    matvec<<<MDIM, 256>>>(P2, vA, ss + 6, vB);   sumsq1024<<<1, 256>>>(vB, ss + 7);
    matvec<<<MDIM, 256>>>(P2, vB, ss + 7, vA);   sumsq1024<<<1, 256>>>(vA, ss + 8);
    matvec<<<MDIM, 256>>>(G,  vA, ss + 8, vB);   sumsq1024<<<1, 256>>>(vB, ss + 9);
    computeEta<<<1, 1>>>(ss + 9, eta);

    // 4) ||Y|| partials
    ynormPart<<<128, 256>>>(Y, ynP);

    // 5) IHT: Gamma=0, residual=-Y, then 51 uniform iterations of 2 kernels
    zeroBuf<<<4096, 256>>>(Gamma, BDIM * MDIM);
    negCopy<<<2048, 256>>>(Y, Resid, BDIM * NDIM);

    for (int t = 0; t < NITER; t++) {
        // Gtmp = Gamma - eta * (Resid @ Wn)   [1024,1024], K=512
        sgemm3<1><<<dim3(16, 8), 256>>>(Resid, Wn, Gtmp, BDIM, MDIM, NDIM, eta, Gamma);
        // Gamma = HT_K(Gtmp); Resid = Gamma @ Wn^T - Y; norm partial
        fusedHT<<<BDIM, 256>>>(Gtmp, Gamma, WnT, Y, Resid, rsP + (size_t)t * BDIM);
    }

    // 6) outputs: X = Wn @ Gamma [512,1024], Gamma [1024,1024], norms [50]
    sgemm3<0><<<dim3(16, 4), 256>>>(Wn, Gamma, out, NDIM, MDIM, MDIM, nullptr, nullptr);
    cudaMemcpyAsync(out + NDIM * MDIM, Gamma, (size_t)BDIM * MDIM * sizeof(float),
                    cudaMemcpyDeviceToDevice);
    normsFinal2<<<50, 256>>>(rsP, ynP, out + NDIM * MDIM + BDIM * MDIM);
}